// round 13
// baseline (speedup 1.0000x reference)
#include <cuda_runtime.h>

// Fixed shapes
#define HH 256
#define WW 512
#define HW (HH * WW)                 // 131072 floats/plane
#define HW4 (HW / 4)                 // 32768 float4/plane
#define HW8 (HW / 8)                 // 16384 float8/plane
#define W4 (WW / 4)                  // 128 float4/row
#define NSTUFF 11
#define STUFF4 (NSTUFF * HW4)
#define STUFF8 (NSTUFF * HW8)
#define ITEMS 8                      // float4 per thread (gather path)
#define ITEMS8 4                     // float8 per thread (bulk paths)
#define TPB 256
#define F4_PER_BLK (TPB * ITEMS)     // 2048 float4 per block (= 16 rows)
#define F8_PER_BLK (TPB * ITEMS8)    // 1024 float8 per block (same 32 KB)
#define ROWS_PER_BLK 16
#define STUFF_BLOCKS (STUFF4 / F4_PER_BLK)   // 176
#define BLOCKS_PER_PLANE (HW4 / F4_PER_BLK)  // 16
#define NBOX 128

// 256-bit global store (Blackwell STG.256). ptr must be 32B-aligned.
__device__ __forceinline__ void stg256(float* p,
    float a0, float a1, float a2, float a3,
    float a4, float a5, float a6, float a7)
{
    asm volatile(
        "st.global.v8.f32 [%0], {%1,%2,%3,%4,%5,%6,%7,%8};"
        :: "l"(p), "f"(a0), "f"(a1), "f"(a2), "f"(a3),
           "f"(a4), "f"(a5), "f"(a6), "f"(a7)
        : "memory");
}

// 256-bit global load (LDG.256, non-coherent).
__device__ __forceinline__ void ldg256(const float* p, float* r)
{
    asm volatile(
        "ld.global.nc.v8.f32 {%0,%1,%2,%3,%4,%5,%6,%7}, [%8];"
        : "=f"(r[0]), "=f"(r[1]), "=f"(r[2]), "=f"(r[3]),
          "=f"(r[4]), "=f"(r[5]), "=f"(r[6]), "=f"(r[7])
        : "l"(p));
}

__global__ __launch_bounds__(TPB) void seg_term_kernel(
    const int*    __restrict__ cls,     // [128]
    const float*  __restrict__ seg,     // [19*HW]
    const float*  __restrict__ boxes,   // [128*5]
    float*        __restrict__ out)
{
    const int b   = blockIdx.x;
    const int tid = threadIdx.x;
    const float4 z = make_float4(0.f, 0.f, 0.f, 0.f);

    if (b < STUFF_BLOCKS) {
        // ---- stuff copy: 4× LDG.256 batched, then 4× STG.256 ----
        const float* s = seg + (size_t)b * F4_PER_BLK * 4;
        float*       o = out + (size_t)b * F4_PER_BLK * 4;
        float v[ITEMS8][8];
        #pragma unroll
        for (int k = 0; k < ITEMS8; k++)
            ldg256(s + (tid + k * TPB) * 8, v[k]);
        #pragma unroll
        for (int k = 0; k < ITEMS8; k++)
            stg256(o + (tid + k * TPB) * 8,
                   v[k][0], v[k][1], v[k][2], v[k][3],
                   v[k][4], v[k][5], v[k][6], v[k][7]);
        return;
    }

    // ---- instance region: each block owns 16 rows of ONE plane ----
    const int ib  = b - STUFF_BLOCKS;
    const int n   = ib >> 4;                     // plane
    const int blk = ib & (BLOCKS_PER_PLANE - 1);
    const int r0  = blk * ROWS_PER_BLK;

    float* obase = out + (size_t)STUFF4 * 4 + (size_t)n * HW + (size_t)blk * F4_PER_BLK * 4;

    const int c = __ldg(cls + n);

    int x0 = 0, y0 = 0, x1 = 0, y1 = 0, m = 0;
    bool any = false;
    if (c != 0) {
        const float* bb = boxes + n * 5;
        x0 = (int)floorf(__ldg(bb + 1) * 0.25f);
        y0 = (int)floorf(__ldg(bb + 2) * 0.25f);
        x1 = (int)(rintf(__ldg(bb + 3) * 0.25f) + 1.0f);  // half-even = jnp.round
        y1 = (int)(rintf(__ldg(bb + 4) * 0.25f) + 1.0f);
        m  = (c + 10 > 18) ? 18 : c + 10;
        any = (y1 > r0) && (y0 < r0 + ROWS_PER_BLK) && (x1 > x0) && (x1 > 0) && (x0 < WW);
    }

    if (!any) {
        // ---- pure-zero chunk: 4× STG.256 ----
        #pragma unroll
        for (int k = 0; k < ITEMS8; k++)
            stg256(obase + (tid + k * TPB) * 8,
                   0.f, 0.f, 0.f, 0.f, 0.f, 0.f, 0.f, 0.f);
        return;
    }

    // ---- box-intersecting chunk: proven float4 gather/mask path ----
    float4* o4 = reinterpret_cast<float4*>(obase);
    const float4* s4 = reinterpret_cast<const float4*>(seg) + m * HW4 + blk * F4_PER_BLK;

    float4 v[ITEMS];
    #pragma unroll
    for (int k = 0; k < ITEMS; k++) {
        const int idx = tid + k * TPB;
        const int y   = r0 + (idx >> 7);
        const int x   = (idx & (W4 - 1)) << 2;

        v[k] = z;
        if (y >= y0 && y < y1) {
            if (x >= x0 && (x + 3) < x1) {
                v[k] = s4[idx];
            } else if ((x + 3) >= x0 && x < x1) {
                const float* sr = reinterpret_cast<const float*>(s4 + idx);
                float vv[4];
                #pragma unroll
                for (int j = 0; j < 4; j++) {
                    const int xx = x + j;
                    vv[j] = (xx >= x0 && xx < x1) ? sr[j] : 0.f;
                }
                v[k] = make_float4(vv[0], vv[1], vv[2], vv[3]);
            }
        }
    }
    #pragma unroll
    for (int k = 0; k < ITEMS; k++) o4[tid + k * TPB] = v[k];
}

extern "C" void kernel_launch(void* const* d_in, const int* in_sizes, int n_in,
                              void* d_out, int out_size)
{
    const int*   cls   = (const int*)d_in[0];
    const float* seg   = (const float*)d_in[1];
    const float* boxes = (const float*)d_in[2];
    float* out = (float*)d_out;

    const int blocks = STUFF_BLOCKS + NBOX * BLOCKS_PER_PLANE;  // 2224
    seg_term_kernel<<<blocks, TPB>>>(cls, seg, boxes, out);
}

// round 14
// speedup vs baseline: 1.0539x; 1.0539x over previous
#include <cuda_runtime.h>

// Fixed shapes
#define HH 256
#define WW 512
#define HW (HH * WW)                 // 131072 floats/plane
#define HW4 (HW / 4)                 // 32768 float4/plane
#define W4 (WW / 4)                  // 128 float4/row
#define NSTUFF 11
#define STUFF4 (NSTUFF * HW4)        // 360448 float4
#define ITEMS 8                      // float4 per thread
#define TPB 256
#define F4_PER_BLK (TPB * ITEMS)     // 2048 float4 per block (= 16 rows)
#define ROWS_PER_BLK (F4_PER_BLK / W4)       // 16
#define STUFF_BLOCKS (STUFF4 / F4_PER_BLK)   // 176 (exact)
#define BLOCKS_PER_PLANE (HW4 / F4_PER_BLK)  // 16 (exact)
#define NBOX 128

__global__ __launch_bounds__(TPB) void seg_term_kernel(
    const int*    __restrict__ cls,     // [128]
    const float*  __restrict__ seg,     // [19*HW]
    const float*  __restrict__ boxes,   // [128*5]
    float*        __restrict__ out)     // [STUFF4*4 + 128*HW]
{
    const int b   = blockIdx.x;
    const int tid = threadIdx.x;
    const float4 z = make_float4(0.f, 0.f, 0.f, 0.f);

    if (b < STUFF_BLOCKS) {
        // ---- stuff copy: 8 batched loads, then 8 stores (MLP=8) ----
        const float4* s4 = reinterpret_cast<const float4*>(seg) + b * F4_PER_BLK;
        float4*       o4 = reinterpret_cast<float4*>(out)       + b * F4_PER_BLK;
        float4 v[ITEMS];
        #pragma unroll
        for (int k = 0; k < ITEMS; k++) v[k] = s4[tid + k * TPB];
        #pragma unroll
        for (int k = 0; k < ITEMS; k++) o4[tid + k * TPB] = v[k];
        return;
    }

    // ---- instance region: each block owns 16 rows of ONE plane ----
    const int ib  = b - STUFF_BLOCKS;
    const int n   = ib >> 4;                     // plane (16 blocks/plane)
    const int blk = ib & (BLOCKS_PER_PLANE - 1);
    const int r0  = blk * ROWS_PER_BLK;          // first row of this block

    float4* o4 = reinterpret_cast<float4*>(out) + STUFF4 + n * HW4 + blk * F4_PER_BLK;

    const int c = __ldg(cls + n);

    int x0 = 0, y0 = 0, x1 = 0, y1 = 0, m = 0;
    bool any = false;
    if (c != 0) {
        const float* bb = boxes + n * 5;
        x0 = (int)floorf(__ldg(bb + 1) * 0.25f);
        y0 = (int)floorf(__ldg(bb + 2) * 0.25f);
        x1 = (int)(rintf(__ldg(bb + 3) * 0.25f) + 1.0f);  // half-even, matches jnp.round
        y1 = (int)(rintf(__ldg(bb + 4) * 0.25f) + 1.0f);
        m  = (c + 10 > 18) ? 18 : c + 10;
        // does this block's row range [r0, r0+16) intersect [y0, y1)?
        any = (y1 > r0) && (y0 < r0 + ROWS_PER_BLK) && (x1 > x0) && (x1 > 0) && (x0 < WW);
    }

    if (!any) {
        // pure zero-fill burst
        #pragma unroll
        for (int k = 0; k < ITEMS; k++) o4[tid + k * TPB] = z;
        return;
    }

    const float4* s4 = reinterpret_cast<const float4*>(seg) + m * HW4 + blk * F4_PER_BLK;

    // Phase 1: compute all 8 values; loads batched up front by ptxas.
    float4 v[ITEMS];
    #pragma unroll
    for (int k = 0; k < ITEMS; k++) {
        const int idx = tid + k * TPB;           // float4 index within chunk
        const int y   = r0 + (idx >> 7);         // global row
        const int x   = (idx & (W4 - 1)) << 2;   // first col of this float4

        v[k] = z;
        if (y >= y0 && y < y1) {
            if (x >= x0 && (x + 3) < x1) {
                v[k] = s4[idx];                  // fully inside
            } else if ((x + 3) >= x0 && x < x1) {
                const float* sr = reinterpret_cast<const float*>(s4 + idx);
                float vv[4];
                #pragma unroll
                for (int j = 0; j < 4; j++) {
                    const int xx = x + j;
                    vv[j] = (xx >= x0 && xx < x1) ? sr[j] : 0.f;
                }
                v[k] = make_float4(vv[0], vv[1], vv[2], vv[3]);
            }
        }
    }
    // Phase 2: store burst
    #pragma unroll
    for (int k = 0; k < ITEMS; k++) o4[tid + k * TPB] = v[k];
}

extern "C" void kernel_launch(void* const* d_in, const int* in_sizes, int n_in,
                              void* d_out, int out_size)
{
    const int*   cls   = (const int*)d_in[0];
    const float* seg   = (const float*)d_in[1];
    const float* boxes = (const float*)d_in[2];
    float* out = (float*)d_out;

    const int blocks = STUFF_BLOCKS + NBOX * BLOCKS_PER_PLANE;  // 176 + 2048 = 2224
    seg_term_kernel<<<blocks, TPB>>>(cls, seg, boxes, out);
}

// round 15
// speedup vs baseline: 1.0562x; 1.0022x over previous
#include <cuda_runtime.h>

// Fixed shapes
#define HH 256
#define WW 512
#define HW (HH * WW)                 // 131072 floats/plane
#define HW4 (HW / 4)                 // 32768 float4/plane
#define W4 (WW / 4)                  // 128 float4/row
#define NSTUFF 11
#define STUFF4 (NSTUFF * HW4)        // 360448 float4
#define ITEMS 4                      // float4 per thread
#define TPB 512
#define F4_PER_BLK (TPB * ITEMS)     // 2048 float4 per block (= 16 rows, 32 KB)
#define ROWS_PER_BLK (F4_PER_BLK / W4)       // 16
#define STUFF_BLOCKS (STUFF4 / F4_PER_BLK)   // 176 (exact)
#define BLOCKS_PER_PLANE (HW4 / F4_PER_BLK)  // 16 (exact)
#define NBOX 128

__global__ __launch_bounds__(TPB) void seg_term_kernel(
    const int*    __restrict__ cls,     // [128]
    const float*  __restrict__ seg,     // [19*HW]
    const float*  __restrict__ boxes,   // [128*5]
    float*        __restrict__ out)     // [STUFF4*4 + 128*HW]
{
    const int b   = blockIdx.x;
    const int tid = threadIdx.x;
    const float4 z = make_float4(0.f, 0.f, 0.f, 0.f);

    if (b < STUFF_BLOCKS) {
        // ---- stuff copy: 4 batched loads, then 4 stores per thread ----
        const float4* s4 = reinterpret_cast<const float4*>(seg) + b * F4_PER_BLK;
        float4*       o4 = reinterpret_cast<float4*>(out)       + b * F4_PER_BLK;
        float4 v[ITEMS];
        #pragma unroll
        for (int k = 0; k < ITEMS; k++) v[k] = s4[tid + k * TPB];
        #pragma unroll
        for (int k = 0; k < ITEMS; k++) o4[tid + k * TPB] = v[k];
        return;
    }

    // ---- instance region: each block owns 16 rows of ONE plane ----
    const int ib  = b - STUFF_BLOCKS;
    const int n   = ib >> 4;                     // plane (16 blocks/plane)
    const int blk = ib & (BLOCKS_PER_PLANE - 1);
    const int r0  = blk * ROWS_PER_BLK;          // first row of this block

    float4* o4 = reinterpret_cast<float4*>(out) + STUFF4 + n * HW4 + blk * F4_PER_BLK;

    const int c = __ldg(cls + n);

    int x0 = 0, y0 = 0, x1 = 0, y1 = 0, m = 0;
    bool any = false;
    if (c != 0) {
        const float* bb = boxes + n * 5;
        x0 = (int)floorf(__ldg(bb + 1) * 0.25f);
        y0 = (int)floorf(__ldg(bb + 2) * 0.25f);
        x1 = (int)(rintf(__ldg(bb + 3) * 0.25f) + 1.0f);  // half-even, matches jnp.round
        y1 = (int)(rintf(__ldg(bb + 4) * 0.25f) + 1.0f);
        m  = (c + 10 > 18) ? 18 : c + 10;
        any = (y1 > r0) && (y0 < r0 + ROWS_PER_BLK) && (x1 > x0) && (x1 > 0) && (x0 < WW);
    }

    if (!any) {
        // pure zero-fill burst
        #pragma unroll
        for (int k = 0; k < ITEMS; k++) o4[tid + k * TPB] = z;
        return;
    }

    const float4* s4 = reinterpret_cast<const float4*>(seg) + m * HW4 + blk * F4_PER_BLK;

    // Phase 1: compute all 4 values; loads batched up front.
    float4 v[ITEMS];
    #pragma unroll
    for (int k = 0; k < ITEMS; k++) {
        const int idx = tid + k * TPB;           // float4 index within chunk
        const int y   = r0 + (idx >> 7);         // global row
        const int x   = (idx & (W4 - 1)) << 2;   // first col of this float4

        v[k] = z;
        if (y >= y0 && y < y1) {
            if (x >= x0 && (x + 3) < x1) {
                v[k] = s4[idx];                  // fully inside
            } else if ((x + 3) >= x0 && x < x1) {
                const float* sr = reinterpret_cast<const float*>(s4 + idx);
                float vv[4];
                #pragma unroll
                for (int j = 0; j < 4; j++) {
                    const int xx = x + j;
                    vv[j] = (xx >= x0 && xx < x1) ? sr[j] : 0.f;
                }
                v[k] = make_float4(vv[0], vv[1], vv[2], vv[3]);
            }
        }
    }
    // Phase 2: store burst
    #pragma unroll
    for (int k = 0; k < ITEMS; k++) o4[tid + k * TPB] = v[k];
}

extern "C" void kernel_launch(void* const* d_in, const int* in_sizes, int n_in,
                              void* d_out, int out_size)
{
    const int*   cls   = (const int*)d_in[0];
    const float* seg   = (const float*)d_in[1];
    const float* boxes = (const float*)d_in[2];
    float* out = (float*)d_out;

    const int blocks = STUFF_BLOCKS + NBOX * BLOCKS_PER_PLANE;  // 176 + 2048 = 2224
    seg_term_kernel<<<blocks, TPB>>>(cls, seg, boxes, out);
}